// round 3
// baseline (speedup 1.0000x reference)
#include <cuda_runtime.h>
#include <math.h>

#define B_   128
#define H_   512
#define E_   256
#define ND_  128
#define V_   5000
#define K0_  384      // E_ + ND_
#define CBLK 125      // logits blocks
#define CPB  40       // vocab cols per logits block (125*40 = 5000)

// ---------------- persistent device state ----------------
__device__ float g_h0T[2][H_ * B_];   // transposed hidden [j][b], ping-pong
__device__ float g_h1T[2][H_ * B_];
__device__ float g_c0[H_ * B_];       // cell state [j][b]
__device__ float g_c1[H_ * B_];
__device__ float g_cval[B_ * 128];    // argmax candidates [b][block]
__device__ int   g_cidx[B_ * 128];

__device__ __forceinline__ float sigmf(float x) { return 1.0f / (1.0f + expf(-x)); }

__global__ void k_init() {
    int i = blockIdx.x * blockDim.x + threadIdx.x;
    if (i < H_ * B_) {
        g_h0T[0][i] = 0.f;
        g_h1T[0][i] = 0.f;
        g_c0[i] = 0.f;
        g_c1[i] = 0.f;
    }
}

// ================= LSTM layer 0 =================
// grid 128, block 512. Each block owns 4 hidden dims j (x 4 gates).
// Thread decomposition: sz = K-slab (4), bg = batch group of 4 (32), cg = j within block (4).
__global__ void __launch_bounds__(512, 1) k_lstm0(
    const float* __restrict__ noise, const float* __restrict__ emb,
    const float* __restrict__ Wih, const float* __restrict__ Whh,
    const float* __restrict__ bih, const float* __restrict__ bhh, int t)
{
    __shared__ float s_red[3 * 2048];
    __shared__ int   s_tok[B_];

    const int tid = threadIdx.x, bid = blockIdx.x;
    const int sz = tid >> 7;          // 0..3
    const int ts = tid & 127;
    const int bg = ts >> 2;           // 0..31
    const int cg = ts & 3;            // 0..3
    const int b0 = bg * 4;
    const int j  = bid * 4 + cg;      // 0..511

    // ---- resolve token for this step ----
    if (t == 0) {
        if (tid < B_) s_tok[tid] = 1;   // start token
    } else {
        int b = tid >> 2, part = tid & 3;
        int lo = part * 32, hi = lo + 32; if (hi > CBLK) hi = CBLK;
        float bv = -3.402823466e38f; int bi = 0x7fffffff;
        const float* cv = &g_cval[b * 128];
        const int*   ci = &g_cidx[b * 128];
        for (int p = lo; p < hi; p++) {
            float v = cv[p]; int ix = ci[p];
            if (v > bv || (v == bv && ix < bi)) { bv = v; bi = ix; }
        }
        #pragma unroll
        for (int off = 2; off >= 1; off >>= 1) {
            float ov = __shfl_down_sync(0xffffffffu, bv, off);
            int   oi = __shfl_down_sync(0xffffffffu, bi, off);
            if (ov > bv || (ov == bv && oi < bi)) { bv = ov; bi = oi; }
        }
        if (part == 0) s_tok[b] = bi;
    }
    __syncthreads();

    const float* h0rd = g_h0T[t & 1];
    float*       h0wr = g_h0T[(t + 1) & 1];

    const float* wA[4]; const float* wAh[4];
    #pragma unroll
    for (int g = 0; g < 4; g++) {
        wA[g]  = Wih + (size_t)(g * H_ + j) * K0_;
        wAh[g] = Whh + (size_t)(g * H_ + j) * H_;
    }

    float acc[16];
    #pragma unroll
    for (int a = 0; a < 16; a++) acc[a] = 0.f;

    // -- embedding segment: k in [sz*64, sz*64+64) of E_=256 --
    {
        const float* xe[4];
        #pragma unroll
        for (int i = 0; i < 4; i++) xe[i] = emb + (size_t)s_tok[b0 + i] * E_;
        int kb = sz * 64;
        #pragma unroll 4
        for (int k = kb; k < kb + 64; k += 4) {
            float4 xv[4], wv[4];
            #pragma unroll
            for (int i = 0; i < 4; i++) xv[i] = *(const float4*)(xe[i] + k);
            #pragma unroll
            for (int g = 0; g < 4; g++) wv[g] = *(const float4*)(wA[g] + k);
            #pragma unroll
            for (int g = 0; g < 4; g++)
                #pragma unroll
                for (int i = 0; i < 4; i++) {
                    acc[g*4+i] += xv[i].x*wv[g].x + xv[i].y*wv[g].y
                                + xv[i].z*wv[g].z + xv[i].w*wv[g].w;
                }
        }
    }
    // -- noise segment: k in [sz*32, sz*32+32) of ND_=128, W cols offset E_ --
    {
        int kb = sz * 32;
        #pragma unroll 4
        for (int k = kb; k < kb + 32; k += 4) {
            float4 xv[4], wv[4];
            #pragma unroll
            for (int i = 0; i < 4; i++) xv[i] = *(const float4*)(noise + (size_t)(b0 + i) * ND_ + k);
            #pragma unroll
            for (int g = 0; g < 4; g++) wv[g] = *(const float4*)(wA[g] + E_ + k);
            #pragma unroll
            for (int g = 0; g < 4; g++)
                #pragma unroll
                for (int i = 0; i < 4; i++) {
                    acc[g*4+i] += xv[i].x*wv[g].x + xv[i].y*wv[g].y
                                + xv[i].z*wv[g].z + xv[i].w*wv[g].w;
                }
        }
    }
    // -- recurrent segment (transposed h layout): k in [sz*128, sz*128+128) --
    {
        int kb = sz * 128;
        #pragma unroll 4
        for (int k = kb; k < kb + 128; k += 4) {
            float4 x0 = *(const float4*)(h0rd + (size_t)(k + 0) * B_ + b0);
            float4 x1 = *(const float4*)(h0rd + (size_t)(k + 1) * B_ + b0);
            float4 x2 = *(const float4*)(h0rd + (size_t)(k + 2) * B_ + b0);
            float4 x3 = *(const float4*)(h0rd + (size_t)(k + 3) * B_ + b0);
            #pragma unroll
            for (int g = 0; g < 4; g++) {
                float4 wv = *(const float4*)(wAh[g] + k);
                acc[g*4+0] += x0.x*wv.x + x1.x*wv.y + x2.x*wv.z + x3.x*wv.w;
                acc[g*4+1] += x0.y*wv.x + x1.y*wv.y + x2.y*wv.z + x3.y*wv.w;
                acc[g*4+2] += x0.z*wv.x + x1.z*wv.y + x2.z*wv.z + x3.z*wv.w;
                acc[g*4+3] += x0.w*wv.x + x1.w*wv.y + x2.w*wv.z + x3.w*wv.w;
            }
        }
    }

    if (sz > 0) {
        float* p = &s_red[(sz - 1) * 2048 + ts * 16];
        #pragma unroll
        for (int a = 0; a < 16; a++) p[a] = acc[a];
    }
    __syncthreads();
    if (sz == 0) {
        #pragma unroll
        for (int a = 0; a < 16; a++)
            acc[a] += s_red[ts*16 + a] + s_red[2048 + ts*16 + a] + s_red[4096 + ts*16 + a];
        float bsum[4];
        #pragma unroll
        for (int g = 0; g < 4; g++) bsum[g] = bih[g * H_ + j] + bhh[g * H_ + j];
        float4 c4 = *(float4*)&g_c0[j * B_ + b0];
        float cc[4] = {c4.x, c4.y, c4.z, c4.w};
        float hh[4];
        #pragma unroll
        for (int i = 0; i < 4; i++) {
            float iv = sigmf(acc[0  + i] + bsum[0]);
            float fv = sigmf(acc[4  + i] + bsum[1]);
            float gv = tanhf(acc[8  + i] + bsum[2]);
            float ov = sigmf(acc[12 + i] + bsum[3]);
            float cn = fv * cc[i] + iv * gv;
            cc[i] = cn;
            hh[i] = ov * tanhf(cn);
        }
        *(float4*)&g_c0[j * B_ + b0]  = make_float4(cc[0], cc[1], cc[2], cc[3]);
        *(float4*)&h0wr[j * B_ + b0]  = make_float4(hh[0], hh[1], hh[2], hh[3]);
    }
}

// ================= LSTM layer 1 =================
__global__ void __launch_bounds__(512, 1) k_lstm1(
    const float* __restrict__ Wih, const float* __restrict__ Whh,
    const float* __restrict__ bih, const float* __restrict__ bhh, int t)
{
    __shared__ float s_red[3 * 2048];
    const int tid = threadIdx.x, bid = blockIdx.x;
    const int sz = tid >> 7, ts = tid & 127;
    const int bg = ts >> 2, cg = ts & 3;
    const int b0 = bg * 4, j = bid * 4 + cg;

    const float* h0n  = g_h0T[(t + 1) & 1];  // written by k_lstm0 this step
    const float* h1rd = g_h1T[t & 1];
    float*       h1wr = g_h1T[(t + 1) & 1];

    const float* wI[4]; const float* wH[4];
    #pragma unroll
    for (int g = 0; g < 4; g++) {
        wI[g] = Wih + (size_t)(g * H_ + j) * H_;
        wH[g] = Whh + (size_t)(g * H_ + j) * H_;
    }

    float acc[16];
    #pragma unroll
    for (int a = 0; a < 16; a++) acc[a] = 0.f;

    int kb = sz * 128;
    #pragma unroll 4
    for (int k = kb; k < kb + 128; k += 4) {
        float4 x0 = *(const float4*)(h0n + (size_t)(k + 0) * B_ + b0);
        float4 x1 = *(const float4*)(h0n + (size_t)(k + 1) * B_ + b0);
        float4 x2 = *(const float4*)(h0n + (size_t)(k + 2) * B_ + b0);
        float4 x3 = *(const float4*)(h0n + (size_t)(k + 3) * B_ + b0);
        #pragma unroll
        for (int g = 0; g < 4; g++) {
            float4 wv = *(const float4*)(wI[g] + k);
            acc[g*4+0] += x0.x*wv.x + x1.x*wv.y + x2.x*wv.z + x3.x*wv.w;
            acc[g*4+1] += x0.y*wv.x + x1.y*wv.y + x2.y*wv.z + x3.y*wv.w;
            acc[g*4+2] += x0.z*wv.x + x1.z*wv.y + x2.z*wv.z + x3.z*wv.w;
            acc[g*4+3] += x0.w*wv.x + x1.w*wv.y + x2.w*wv.z + x3.w*wv.w;
        }
    }
    #pragma unroll 4
    for (int k = kb; k < kb + 128; k += 4) {
        float4 x0 = *(const float4*)(h1rd + (size_t)(k + 0) * B_ + b0);
        float4 x1 = *(const float4*)(h1rd + (size_t)(k + 1) * B_ + b0);
        float4 x2 = *(const float4*)(h1rd + (size_t)(k + 2) * B_ + b0);
        float4 x3 = *(const float4*)(h1rd + (size_t)(k + 3) * B_ + b0);
        #pragma unroll
        for (int g = 0; g < 4; g++) {
            float4 wv = *(const float4*)(wH[g] + k);
            acc[g*4+0] += x0.x*wv.x + x1.x*wv.y + x2.x*wv.z + x3.x*wv.w;
            acc[g*4+1] += x0.y*wv.x + x1.y*wv.y + x2.y*wv.z + x3.y*wv.w;
            acc[g*4+2] += x0.z*wv.x + x1.z*wv.y + x2.z*wv.z + x3.z*wv.w;
            acc[g*4+3] += x0.w*wv.x + x1.w*wv.y + x2.w*wv.z + x3.w*wv.w;
        }
    }

    if (sz > 0) {
        float* p = &s_red[(sz - 1) * 2048 + ts * 16];
        #pragma unroll
        for (int a = 0; a < 16; a++) p[a] = acc[a];
    }
    __syncthreads();
    if (sz == 0) {
        #pragma unroll
        for (int a = 0; a < 16; a++)
            acc[a] += s_red[ts*16 + a] + s_red[2048 + ts*16 + a] + s_red[4096 + ts*16 + a];
        float bsum[4];
        #pragma unroll
        for (int g = 0; g < 4; g++) bsum[g] = bih[g * H_ + j] + bhh[g * H_ + j];
        float4 c4 = *(float4*)&g_c1[j * B_ + b0];
        float cc[4] = {c4.x, c4.y, c4.z, c4.w};
        float hh[4];
        #pragma unroll
        for (int i = 0; i < 4; i++) {
            float iv = sigmf(acc[0  + i] + bsum[0]);
            float fv = sigmf(acc[4  + i] + bsum[1]);
            float gv = tanhf(acc[8  + i] + bsum[2]);
            float ov = sigmf(acc[12 + i] + bsum[3]);
            float cn = fv * cc[i] + iv * gv;
            cc[i] = cn;
            hh[i] = ov * tanhf(cn);
        }
        *(float4*)&g_c1[j * B_ + b0] = make_float4(cc[0], cc[1], cc[2], cc[3]);
        *(float4*)&h1wr[j * B_ + b0] = make_float4(hh[0], hh[1], hh[2], hh[3]);
    }
}

// ================= logits + partial argmax =================
// grid 125, block 512. Block handles 40 vocab cols; thread: 2 K-slabs x 32 bgroups x 8 colgroups(5 cols).
__global__ void __launch_bounds__(512, 1) k_logits(
    const float* __restrict__ Wout, const float* __restrict__ bout,
    float* __restrict__ out, int t, int T)
{
    __shared__ float s_red[256 * 20];
    __shared__ float s_cv[8 * 128];
    __shared__ int   s_ci[8 * 128];

    const int tid = threadIdx.x, bid = blockIdx.x;
    const int kz = tid >> 8;          // 0,1
    const int t2 = tid & 255;
    const int cbg = t2 >> 3;          // 0..31
    const int ccg = t2 & 7;           // 0..7
    const int b0 = cbg * 4;
    const int cbase = bid * CPB + ccg * 5;

    const float* h1 = g_h1T[(t + 1) & 1];

    const float* wp[5];
    #pragma unroll
    for (int q = 0; q < 5; q++) wp[q] = Wout + (size_t)(cbase + q) * H_;

    float acc[20];
    #pragma unroll
    for (int a = 0; a < 20; a++) acc[a] = 0.f;

    int kb = kz * 256;
    #pragma unroll 4
    for (int k = kb; k < kb + 256; k += 4) {
        float4 x0 = *(const float4*)(h1 + (size_t)(k + 0) * B_ + b0);
        float4 x1 = *(const float4*)(h1 + (size_t)(k + 1) * B_ + b0);
        float4 x2 = *(const float4*)(h1 + (size_t)(k + 2) * B_ + b0);
        float4 x3 = *(const float4*)(h1 + (size_t)(k + 3) * B_ + b0);
        #pragma unroll
        for (int q = 0; q < 5; q++) {
            float4 wv = *(const float4*)(wp[q] + k);
            acc[q*4+0] += x0.x*wv.x + x1.x*wv.y + x2.x*wv.z + x3.x*wv.w;
            acc[q*4+1] += x0.y*wv.x + x1.y*wv.y + x2.y*wv.z + x3.y*wv.w;
            acc[q*4+2] += x0.z*wv.x + x1.z*wv.y + x2.z*wv.z + x3.z*wv.w;
            acc[q*4+3] += x0.w*wv.x + x1.w*wv.y + x2.w*wv.z + x3.w*wv.w;
        }
    }

    if (kz == 1) {
        float* p = &s_red[t2 * 20];
        #pragma unroll
        for (int a = 0; a < 20; a++) p[a] = acc[a];
    }
    __syncthreads();
    if (kz == 0) {
        #pragma unroll
        for (int a = 0; a < 20; a++) acc[a] += s_red[t2 * 20 + a];
        float bb[5];
        #pragma unroll
        for (int q = 0; q < 5; q++) bb[q] = bout[cbase + q];
        #pragma unroll
        for (int i = 0; i < 4; i++) {
            float bv = -3.402823466e38f; int bix = 0;
            float* op = out + ((size_t)(b0 + i) * T + t) * V_ + cbase;
            #pragma unroll
            for (int q = 0; q < 5; q++) {
                float v = acc[q*4+i] + bb[q];
                op[q] = v;
                if (v > bv) { bv = v; bix = cbase + q; }  // ascending idx: > keeps first max
            }
            s_cv[ccg * 128 + b0 + i] = bv;
            s_ci[ccg * 128 + b0 + i] = bix;
        }
    }
    __syncthreads();
    if (tid < 128) {
        int b = tid;
        float bv = -3.402823466e38f; int bi = 0x7fffffff;
        #pragma unroll
        for (int p = 0; p < 8; p++) {
            float v = s_cv[p * 128 + b]; int ix = s_ci[p * 128 + b];
            if (v > bv || (v == bv && ix < bi)) { bv = v; bi = ix; }
        }
        g_cval[b * 128 + bid] = bv;
        g_cidx[b * 128 + bid] = bi;
    }
}

// ================= final heads (att + soph) =================
__global__ void k_head(const float* __restrict__ Watt, const float* __restrict__ batt,
                       const float* __restrict__ Wsoph, const float* __restrict__ bsoph,
                       float* __restrict__ out, int T)
{
    const float* h1 = g_h1T[T & 1];
    int m = blockIdx.x;          // 0..23
    int b = threadIdx.x;         // 0..127
    size_t base = (size_t)B_ * T * V_;
    const float* w; float bias; float* op;
    if (m < 8) {
        w = Watt + m * H_; bias = batt[m];
        op = out + base + (size_t)b * 8 + m;
    } else {
        int mm = m - 8;
        w = Wsoph + mm * H_; bias = bsoph[mm];
        op = out + base + (size_t)B_ * 8 + (size_t)b * 16 + mm;
    }
    float a = 0.f;
    #pragma unroll 4
    for (int k = 0; k < H_; k += 4) {
        float4 wv = *(const float4*)(w + k);
        a += h1[(k + 0) * B_ + b] * wv.x + h1[(k + 1) * B_ + b] * wv.y
           + h1[(k + 2) * B_ + b] * wv.z + h1[(k + 3) * B_ + b] * wv.w;
    }
    *op = a + bias;
}

// ================= launch =================
extern "C" void kernel_launch(void* const* d_in, const int* in_sizes, int n_in,
                              void* d_out, int out_size)
{
    const float* noise = (const float*)d_in[0];
    const float* emb   = (const float*)d_in[1];
    const float* Wih0  = (const float*)d_in[2];
    const float* Whh0  = (const float*)d_in[3];
    const float* bih0  = (const float*)d_in[4];
    const float* bhh0  = (const float*)d_in[5];
    const float* Wih1  = (const float*)d_in[6];
    const float* Whh1  = (const float*)d_in[7];
    const float* bih1  = (const float*)d_in[8];
    const float* bhh1  = (const float*)d_in[9];
    const float* Wout  = (const float*)d_in[10];
    const float* bout  = (const float*)d_in[11];
    const float* Watt  = (const float*)d_in[12];
    const float* batt  = (const float*)d_in[13];
    const float* Wsoph = (const float*)d_in[14];
    const float* bsoph = (const float*)d_in[15];
    float* out = (float*)d_out;

    // out layout: [B,T,V] payload | [B,8] att | [B,16] soph
    int T = (out_size - B_ * 24) / (B_ * V_);
    if (T <= 0) T = 200;

    k_init<<<(H_ * B_ + 255) / 256, 256>>>();
    for (int t = 0; t < T; t++) {
        k_lstm0<<<128, 512>>>(noise, emb, Wih0, Whh0, bih0, bhh0, t);
        k_lstm1<<<128, 512>>>(Wih1, Whh1, bih1, bhh1, t);
        k_logits<<<CBLK, 512>>>(Wout, bout, out, t, T);
    }
    k_head<<<24, 128>>>(Watt, batt, Wsoph, bsoph, out, T);
}

// round 4
// speedup vs baseline: 2.0114x; 2.0114x over previous
#include <cuda_runtime.h>
#include <math.h>
#include <float.h>

#define B_   128
#define H_   512
#define E_   256
#define ND_  128
#define V_   5000
#define K0_  384      // E_ + ND_

typedef unsigned long long u64;

// ---------------- persistent device state ----------------
__device__ __align__(16) float g_h0T[2][H_ * B_];   // [k][b], ping-pong
__device__ __align__(16) float g_h1T[2][H_ * B_];
__device__ __align__(16) float g_c0[H_ * B_];
__device__ __align__(16) float g_c1[H_ * B_];
__device__ __align__(16) float g_x0[K0_ * B_];      // [k][b]: emb(0..255) per step, noise(256..383) static
__device__ __align__(16) float g_cval[128 * B_];    // [p][b]  (p = logits block)
__device__ int   g_cidx[128 * B_];

__device__ __forceinline__ float sigmf(float x) { return 1.0f / (1.0f + expf(-x)); }

__device__ __forceinline__ u64 dup2(float a) {
    u64 r; asm("mov.b64 %0,{%1,%1};" : "=l"(r) : "f"(a)); return r;
}
__device__ __forceinline__ void fma2(u64& d, u64 x, u64 w) {
    asm("fma.rn.f32x2 %0,%1,%2,%0;" : "+l"(d) : "l"(x), "l"(w));
}
__device__ __forceinline__ u64 add2(u64 a, u64 b) {
    u64 r; asm("add.rn.f32x2 %0,%1,%2;" : "=l"(r) : "l"(a), "l"(b)); return r;
}
__device__ __forceinline__ void unpack2(u64 a, float& x, float& y) {
    asm("mov.b64 {%0,%1},%2;" : "=f"(x), "=f"(y) : "l"(a));
}

// 8-row GEMM slab body: rows' weight ptrs W0..W7 (warp-uniform), x in [k][B_] layout.
// acc[16] = [row r][batch-pair p]; lane4 = lane*4.
#define ROWF(WP, AI) do {                                              \
    float4 wv_ = *(const float4*)((WP) + k);                           \
    u64 wa_ = dup2(wv_.x), wb_ = dup2(wv_.y),                          \
        wc_ = dup2(wv_.z), wd_ = dup2(wv_.w);                          \
    fma2(acc[(AI)*2+0], xq0.x, wa_); fma2(acc[(AI)*2+1], xq0.y, wa_);  \
    fma2(acc[(AI)*2+0], xq1.x, wb_); fma2(acc[(AI)*2+1], xq1.y, wb_);  \
    fma2(acc[(AI)*2+0], xq2.x, wc_); fma2(acc[(AI)*2+1], xq2.y, wc_);  \
    fma2(acc[(AI)*2+0], xq3.x, wd_); fma2(acc[(AI)*2+1], xq3.y, wd_);  \
} while (0)

#define SEG8(XB, W0,W1,W2,W3,W4,W5,W6,W7, KLO, KLEN) do {              \
    const float* xb_ = (XB);                                           \
    _Pragma("unroll 2")                                                \
    for (int k = (KLO); k < (KLO) + (KLEN); k += 4) {                  \
        ulonglong2 xq0 = *(const ulonglong2*)(xb_ + (size_t)(k+0)*B_ + lane4); \
        ulonglong2 xq1 = *(const ulonglong2*)(xb_ + (size_t)(k+1)*B_ + lane4); \
        ulonglong2 xq2 = *(const ulonglong2*)(xb_ + (size_t)(k+2)*B_ + lane4); \
        ulonglong2 xq3 = *(const ulonglong2*)(xb_ + (size_t)(k+3)*B_ + lane4); \
        ROWF(W0,0); ROWF(W1,1); ROWF(W2,2); ROWF(W3,3);                \
        ROWF(W4,4); ROWF(W5,5); ROWF(W6,6); ROWF(W7,7);                \
    }                                                                  \
} while (0)

// ================= init: zero state, transpose noise =================
__global__ void k_init(const float* __restrict__ noise) {
    int i = blockIdx.x * 256 + threadIdx.x;
    if (i < H_ * B_) {
        g_h0T[0][i] = 0.f; g_h1T[0][i] = 0.f;
        g_c0[i] = 0.f;     g_c1[i] = 0.f;
    }
    if (i < ND_ * B_) {
        int k = i >> 7, b = i & 127;
        g_x0[(E_ + k) * B_ + b] = noise[b * ND_ + k];
    }
}

// ================= token reduce + embedding gather/transpose =================
// grid 64, block 128. Each block: reduce token per b (coalesced over [p][b]), then
// write g_x0[k0..k0+3][b] from emb[token[b]].
__global__ void k_gather(const float* __restrict__ emb, int t) {
    int b = threadIdx.x;
    int tok = 1;
    if (t > 0) {
        float bv = -FLT_MAX; int bi = 0x7fffffff;
        for (int p = 0; p < 125; p++) {
            float v = g_cval[p * B_ + b]; int ix = g_cidx[p * B_ + b];
            if (v > bv || (v == bv && ix < bi)) { bv = v; bi = ix; }
        }
        tok = bi;
    }
    int k0 = blockIdx.x * 4;
    float4 e = *(const float4*)(emb + (size_t)tok * E_ + k0);
    g_x0[(k0 + 0) * B_ + b] = e.x;
    g_x0[(k0 + 1) * B_ + b] = e.y;
    g_x0[(k0 + 2) * B_ + b] = e.z;
    g_x0[(k0 + 3) * B_ + b] = e.w;
}

// ================= LSTM layers =================
// grid 128, block 256 = 8 warps = 4 kz x 2 rw. Warp rows = 4 gates x 2 j.
// Lane owns 4 batch (lane4..lane4+3). acc[16] = [g*2+jj][pair].

__device__ __forceinline__ void lstm_epilogue(
    u64 acc[16], const float* __restrict__ bih, const float* __restrict__ bhh,
    float* __restrict__ cst, float* __restrict__ hwr, int jbase, int lane4)
{
    #pragma unroll
    for (int jj = 0; jj < 2; jj++) {
        int j = jbase + jj;
        float gv[4][4];
        #pragma unroll
        for (int g = 0; g < 4; g++) {
            unpack2(acc[(g*2+jj)*2 + 0], gv[g][0], gv[g][1]);
            unpack2(acc[(g*2+jj)*2 + 1], gv[g][2], gv[g][3]);
        }
        float bsum[4];
        #pragma unroll
        for (int g = 0; g < 4; g++) bsum[g] = bih[g * H_ + j] + bhh[g * H_ + j];
        float4 c4 = *(float4*)&cst[j * B_ + lane4];
        float cc[4] = {c4.x, c4.y, c4.z, c4.w};
        float hh[4];
        #pragma unroll
        for (int i = 0; i < 4; i++) {
            float iv = sigmf(gv[0][i] + bsum[0]);
            float fv = sigmf(gv[1][i] + bsum[1]);
            float gg = tanhf(gv[2][i] + bsum[2]);
            float ov = sigmf(gv[3][i] + bsum[3]);
            float cn = fv * cc[i] + iv * gg;
            cc[i] = cn;
            hh[i] = ov * tanhf(cn);
        }
        *(float4*)&cst[j * B_ + lane4] = make_float4(cc[0], cc[1], cc[2], cc[3]);
        *(float4*)&hwr[j * B_ + lane4] = make_float4(hh[0], hh[1], hh[2], hh[3]);
    }
}

__global__ void __launch_bounds__(256, 1) k_lstm0(
    const float* __restrict__ Wih, const float* __restrict__ Whh,
    const float* __restrict__ bih, const float* __restrict__ bhh, int t)
{
    __shared__ u64 sred[6][32][16];
    const int tid = threadIdx.x, lane = tid & 31, wid = tid >> 5;
    const int kz = wid >> 1, rw = wid & 1;
    const int lane4 = lane * 4;
    const int jbase = blockIdx.x * 4 + rw * 2;

    const float* h0rd = g_h0T[t & 1];
    float*       h0wr = g_h0T[(t + 1) & 1];

    u64 acc[16];
    #pragma unroll
    for (int a = 0; a < 16; a++) acc[a] = 0ull;

    // rows r = g*2+jj -> weight row (g*H_ + jbase + jj)
    {
        const float* w0 = Wih + (size_t)(0*H_ + jbase + 0) * K0_;
        const float* w1 = Wih + (size_t)(0*H_ + jbase + 1) * K0_;
        const float* w2 = Wih + (size_t)(1*H_ + jbase + 0) * K0_;
        const float* w3 = Wih + (size_t)(1*H_ + jbase + 1) * K0_;
        const float* w4 = Wih + (size_t)(2*H_ + jbase + 0) * K0_;
        const float* w5 = Wih + (size_t)(2*H_ + jbase + 1) * K0_;
        const float* w6 = Wih + (size_t)(3*H_ + jbase + 0) * K0_;
        const float* w7 = Wih + (size_t)(3*H_ + jbase + 1) * K0_;
        SEG8(g_x0, w0,w1,w2,w3,w4,w5,w6,w7, kz * 96, 96);
    }
    {
        const float* w0 = Whh + (size_t)(0*H_ + jbase + 0) * H_;
        const float* w1 = Whh + (size_t)(0*H_ + jbase + 1) * H_;
        const float* w2 = Whh + (size_t)(1*H_ + jbase + 0) * H_;
        const float* w3 = Whh + (size_t)(1*H_ + jbase + 1) * H_;
        const float* w4 = Whh + (size_t)(2*H_ + jbase + 0) * H_;
        const float* w5 = Whh + (size_t)(2*H_ + jbase + 1) * H_;
        const float* w6 = Whh + (size_t)(3*H_ + jbase + 0) * H_;
        const float* w7 = Whh + (size_t)(3*H_ + jbase + 1) * H_;
        SEG8(h0rd, w0,w1,w2,w3,w4,w5,w6,w7, kz * 128, 128);
    }

    if (kz > 0) {
        #pragma unroll
        for (int a = 0; a < 16; a++) sred[(kz - 1) * 2 + rw][lane][a] = acc[a];
    }
    __syncthreads();
    if (kz == 0) {
        #pragma unroll
        for (int s = 0; s < 3; s++)
            #pragma unroll
            for (int a = 0; a < 16; a++)
                acc[a] = add2(acc[a], sred[s * 2 + rw][lane][a]);
        lstm_epilogue(acc, bih, bhh, g_c0, h0wr, jbase, lane4);
    }
}

__global__ void __launch_bounds__(256, 1) k_lstm1(
    const float* __restrict__ Wih, const float* __restrict__ Whh,
    const float* __restrict__ bih, const float* __restrict__ bhh, int t)
{
    __shared__ u64 sred[6][32][16];
    const int tid = threadIdx.x, lane = tid & 31, wid = tid >> 5;
    const int kz = wid >> 1, rw = wid & 1;
    const int lane4 = lane * 4;
    const int jbase = blockIdx.x * 4 + rw * 2;

    const float* h0n  = g_h0T[(t + 1) & 1];
    const float* h1rd = g_h1T[t & 1];
    float*       h1wr = g_h1T[(t + 1) & 1];

    u64 acc[16];
    #pragma unroll
    for (int a = 0; a < 16; a++) acc[a] = 0ull;

    {
        const float* w0 = Wih + (size_t)(0*H_ + jbase + 0) * H_;
        const float* w1 = Wih + (size_t)(0*H_ + jbase + 1) * H_;
        const float* w2 = Wih + (size_t)(1*H_ + jbase + 0) * H_;
        const float* w3 = Wih + (size_t)(1*H_ + jbase + 1) * H_;
        const float* w4 = Wih + (size_t)(2*H_ + jbase + 0) * H_;
        const float* w5 = Wih + (size_t)(2*H_ + jbase + 1) * H_;
        const float* w6 = Wih + (size_t)(3*H_ + jbase + 0) * H_;
        const float* w7 = Wih + (size_t)(3*H_ + jbase + 1) * H_;
        SEG8(h0n, w0,w1,w2,w3,w4,w5,w6,w7, kz * 128, 128);
    }
    {
        const float* w0 = Whh + (size_t)(0*H_ + jbase + 0) * H_;
        const float* w1 = Whh + (size_t)(0*H_ + jbase + 1) * H_;
        const float* w2 = Whh + (size_t)(1*H_ + jbase + 0) * H_;
        const float* w3 = Whh + (size_t)(1*H_ + jbase + 1) * H_;
        const float* w4 = Whh + (size_t)(2*H_ + jbase + 0) * H_;
        const float* w5 = Whh + (size_t)(2*H_ + jbase + 1) * H_;
        const float* w6 = Whh + (size_t)(3*H_ + jbase + 0) * H_;
        const float* w7 = Whh + (size_t)(3*H_ + jbase + 1) * H_;
        SEG8(h1rd, w0,w1,w2,w3,w4,w5,w6,w7, kz * 128, 128);
    }

    if (kz > 0) {
        #pragma unroll
        for (int a = 0; a < 16; a++) sred[(kz - 1) * 2 + rw][lane][a] = acc[a];
    }
    __syncthreads();
    if (kz == 0) {
        #pragma unroll
        for (int s = 0; s < 3; s++)
            #pragma unroll
            for (int a = 0; a < 16; a++)
                acc[a] = add2(acc[a], sred[s * 2 + rw][lane][a]);
        lstm_epilogue(acc, bih, bhh, g_c1, h1wr, jbase, lane4);
    }
}

// ================= logits + partial argmax =================
// grid 125, block 512 = 16 warps = 2 kz x 8 rw. Warp: 5 vocab rows x 128 batch.
__global__ void __launch_bounds__(512, 1) k_logits(
    const float* __restrict__ Wout, const float* __restrict__ bout,
    float* __restrict__ out, int t, int T)
{
    __shared__ u64   sred[8][32][10];
    __shared__ float s_cv[8][B_];
    __shared__ int   s_ci[8][B_];

    const int tid = threadIdx.x, lane = tid & 31, wid = tid >> 5;
    const int kz = wid >> 3, rw = wid & 7;
    const int lane4 = lane * 4;
    const int cbase = blockIdx.x * 40 + rw * 5;

    const float* h1 = g_h1T[(t + 1) & 1];
    const float* w0 = Wout + (size_t)(cbase + 0) * H_;
    const float* w1 = Wout + (size_t)(cbase + 1) * H_;
    const float* w2 = Wout + (size_t)(cbase + 2) * H_;
    const float* w3 = Wout + (size_t)(cbase + 3) * H_;
    const float* w4 = Wout + (size_t)(cbase + 4) * H_;

    u64 acc[10];
    #pragma unroll
    for (int a = 0; a < 10; a++) acc[a] = 0ull;

    {
        const float* xb_ = h1;
        #pragma unroll 2
        for (int k = kz * 256; k < kz * 256 + 256; k += 4) {
            ulonglong2 xq0 = *(const ulonglong2*)(xb_ + (size_t)(k+0)*B_ + lane4);
            ulonglong2 xq1 = *(const ulonglong2*)(xb_ + (size_t)(k+1)*B_ + lane4);
            ulonglong2 xq2 = *(const ulonglong2*)(xb_ + (size_t)(k+2)*B_ + lane4);
            ulonglong2 xq3 = *(const ulonglong2*)(xb_ + (size_t)(k+3)*B_ + lane4);
            ROWF(w0,0); ROWF(w1,1); ROWF(w2,2); ROWF(w3,3); ROWF(w4,4);
        }
    }

    if (kz == 1) {
        #pragma unroll
        for (int a = 0; a < 10; a++) sred[rw][lane][a] = acc[a];
    }
    __syncthreads();
    if (kz == 0) {
        #pragma unroll
        for (int a = 0; a < 10; a++) acc[a] = add2(acc[a], sred[rw][lane][a]);

        float vals[5][4];
        #pragma unroll
        for (int q = 0; q < 5; q++) {
            float bq = bout[cbase + q];
            float v0, v1, v2, v3;
            unpack2(acc[q*2+0], v0, v1);
            unpack2(acc[q*2+1], v2, v3);
            vals[q][0] = v0 + bq; vals[q][1] = v1 + bq;
            vals[q][2] = v2 + bq; vals[q][3] = v3 + bq;
        }
        #pragma unroll
        for (int i = 0; i < 4; i++) {
            int b = lane4 + i;
            float* op = out + ((size_t)b * T + t) * V_ + cbase;
            float bv = -FLT_MAX; int bix = 0;
            #pragma unroll
            for (int q = 0; q < 5; q++) {
                float v = vals[q][i];
                op[q] = v;
                if (v > bv) { bv = v; bix = cbase + q; }   // ascending idx keeps first max
            }
            s_cv[rw][b] = bv;
            s_ci[rw][b] = bix;
        }
    }
    __syncthreads();
    if (tid < B_) {
        int b = tid;
        float bv = -FLT_MAX; int bi = 0x7fffffff;
        #pragma unroll
        for (int p = 0; p < 8; p++) {
            float v = s_cv[p][b]; int ix = s_ci[p][b];
            if (v > bv || (v == bv && ix < bi)) { bv = v; bi = ix; }
        }
        g_cval[blockIdx.x * B_ + b] = bv;
        g_cidx[blockIdx.x * B_ + b] = bi;
    }
}

// ================= final heads =================
__global__ void k_head(const float* __restrict__ Watt, const float* __restrict__ batt,
                       const float* __restrict__ Wsoph, const float* __restrict__ bsoph,
                       float* __restrict__ out, int T)
{
    const float* h1 = g_h1T[T & 1];
    int m = blockIdx.x;          // 0..23
    int b = threadIdx.x;         // 0..127
    size_t base = (size_t)B_ * T * V_;
    const float* w; float bias; float* op;
    if (m < 8) {
        w = Watt + m * H_; bias = batt[m];
        op = out + base + (size_t)b * 8 + m;
    } else {
        int mm = m - 8;
        w = Wsoph + mm * H_; bias = bsoph[mm];
        op = out + base + (size_t)B_ * 8 + (size_t)b * 16 + mm;
    }
    float a = 0.f;
    #pragma unroll 4
    for (int k = 0; k < H_; k += 4) {
        float4 wv = *(const float4*)(w + k);
        a += h1[(k + 0) * B_ + b] * wv.x + h1[(k + 1) * B_ + b] * wv.y
           + h1[(k + 2) * B_ + b] * wv.z + h1[(k + 3) * B_ + b] * wv.w;
    }
    *op = a + bias;
}

// ================= launch =================
extern "C" void kernel_launch(void* const* d_in, const int* in_sizes, int n_in,
                              void* d_out, int out_size)
{
    const float* noise = (const float*)d_in[0];
    const float* emb   = (const float*)d_in[1];
    const float* Wih0  = (const float*)d_in[2];
    const float* Whh0  = (const float*)d_in[3];
    const float* bih0  = (const float*)d_in[4];
    const float* bhh0  = (const float*)d_in[5];
    const float* Wih1  = (const float*)d_in[6];
    const float* Whh1  = (const float*)d_in[7];
    const float* bih1  = (const float*)d_in[8];
    const float* bhh1  = (const float*)d_in[9];
    const float* Wout  = (const float*)d_in[10];
    const float* bout  = (const float*)d_in[11];
    const float* Watt  = (const float*)d_in[12];
    const float* batt  = (const float*)d_in[13];
    const float* Wsoph = (const float*)d_in[14];
    const float* bsoph = (const float*)d_in[15];
    float* out = (float*)d_out;

    int T = (out_size - B_ * 24) / (B_ * V_);
    if (T <= 0) T = 200;

    k_init<<<256, 256>>>(noise);
    for (int t = 0; t < T; t++) {
        k_gather<<<64, 128>>>(emb, t);
        k_lstm0<<<128, 256>>>(Wih0, Whh0, bih0, bhh0, t);
        k_lstm1<<<128, 256>>>(Wih1, Whh1, bih1, bhh1, t);
        k_logits<<<125, 512>>>(Wout, bout, out, t, T);
    }
    k_head<<<24, 128>>>(Watt, batt, Wsoph, bsoph, out, T);
}